// round 10
// baseline (speedup 1.0000x reference)
#include <cuda_runtime.h>
#include <cstdint>

#define BH   32
#define LSEQ 4096
#define DK   16
#define DV   64
#define CS   256
#define NC   16

// Symmetric-pair state: 136 pair rows (d<=e) + 16 linear rows + 1 ones row,
// padded to 160 rows x 72 cols (64 v-cols + 1 aux-sum col + 7 zero pads).
#define NP   160
#define NW   72
#define ST_STRIDE (NP * NW)   // 11520

__device__ float g_state[(size_t)BH * NC * ST_STRIDE];

__device__ __forceinline__ unsigned f2t(float x) {
    unsigned u;
    asm("cvt.rna.tf32.f32 %0, %1;" : "=r"(u) : "f"(x));
    return u;
}
__device__ __forceinline__ float f2tf(float x) { return __uint_as_float(f2t(x)); }
__device__ __forceinline__ unsigned fas(float x) { return __float_as_uint(x); }
__device__ __forceinline__ unsigned shflu(unsigned v, int src) {
    return __shfl_sync(0xffffffffu, v, src);
}

__device__ __forceinline__ void mma8(float* c, unsigned a0, unsigned a1,
                                     unsigned a2, unsigned a3,
                                     unsigned b0, unsigned b1) {
    asm volatile(
        "mma.sync.aligned.m16n8k8.row.col.f32.tf32.tf32.f32 "
        "{%0,%1,%2,%3},{%4,%5,%6,%7},{%8,%9},{%0,%1,%2,%3};"
        : "+f"(c[0]), "+f"(c[1]), "+f"(c[2]), "+f"(c[3])
        : "r"(a0), "r"(a1), "r"(a2), "r"(a3), "r"(b0), "r"(b1));
}

// p -> (d, e, w).  d,e in [0,16]; index 16 hits the pad column (=1.0f).
__device__ __forceinline__ void lut_build(int* spd, int* spe, float* sw, int tid) {
    if (tid < NP) {
        int p = tid, d = 0, e;
        float w;
        if (p < 136) {
            int base = 0;
            while (base + (16 - d) <= p) { base += 16 - d; d++; }
            e = d + (p - base);
            w = (d == e) ? 0.5f : 1.0f;
        } else if (p < 152) { d = p - 136; e = 16; w = 1.f; }
        else if (p == 152) { d = 16; e = 16; w = 1.f; }
        else               { d = 16; e = 16; w = 0.f; }
        spd[p] = d; spe[p] = e; sw[p] = w;
    }
}

// ---------------------------------------------------------------------------
// Kernel 1: state build = single GEMM  st[160x72] = A[160x256] @ B[256x72]
// Full B staged once (raw fp32; mma truncates); ONE barrier; 32-step stream.
// 480 threads = 15 warps, 2 CTAs/SM (regs capped).
// ---------------------------------------------------------------------------
__global__ __launch_bounds__(480, 2)
void k_build(const float* __restrict__ kin, const float* __restrict__ vin) {
    const int head = blockIdx.x, ch = blockIdx.y;
    extern __shared__ float sm[];
    float* sk = sm;                     // [256][17], col 16 = 1.0 pad
    float* sB = sk + CS * 17;           // [256][72] full V + aux
    int*   spd = (int*)(sB + CS * NW);  // [160]
    int*   spe = spd + NP;              // [160]
    float* sw  = (float*)(spe + NP);    // [160]
    unsigned* sBu = (unsigned*)sB;

    const float* kg = kin + ((size_t)head * LSEQ + (size_t)ch * CS) * DK;
    const float* vg = vin + ((size_t)head * LSEQ + (size_t)ch * CS) * DV;
    float* st = g_state + (size_t)(head * NC + ch) * ST_STRIDE;

    const int tid = threadIdx.x, warp = tid >> 5, lane = tid & 31;
    const int wm = warp / 3, wn = warp % 3, g = lane >> 2, tg = lane & 3;
    const int rb = 32 * wm, cb = 24 * wn;

    for (int i = tid; i < CS * DK; i += 480)
        sk[(i >> 4) * 17 + (i & 15)] = f2tf(kg[i]);
    for (int i = tid; i < CS; i += 480) sk[i * 17 + 16] = 1.0f;
    for (int i = tid; i < CS * 18; i += 480) {
        int cc = i / 18, f4 = (i - cc * 18) * 4;
        uint4 w;
        if (f4 < 64) {
            w = *(const uint4*)&vg[cc * 64 + f4];     // raw fp32 (HW truncates)
        } else {
            w = make_uint4(f4 == 64 ? 0x3f800000u : 0u, 0u, 0u, 0u);
        }
        *(uint4*)&sBu[cc * NW + f4] = w;
    }
    lut_build(spd, spe, sw, tid);
    __syncthreads();

    int rd[2][2], re[2][2];
    #pragma unroll
    for (int mt = 0; mt < 2; mt++) {
        int r0 = rb + 16 * mt + g;
        rd[mt][0] = spd[r0];     re[mt][0] = spe[r0];
        rd[mt][1] = spd[r0 + 8]; re[mt][1] = spe[r0 + 8];
    }

    float c[2][3][4];
    #pragma unroll
    for (int mt = 0; mt < 2; mt++)
        #pragma unroll
        for (int nt = 0; nt < 3; nt++)
            #pragma unroll
            for (int u = 0; u < 4; u++) c[mt][nt][u] = 0.f;

    #pragma unroll 4
    for (int ks = 0; ks < 32; ks++) {
        const float* p0 = sk + (8 * ks + tg) * 17;
        const float* p1 = p0 + 4 * 17;
        unsigned a[2][4];
        #pragma unroll
        for (int mt = 0; mt < 2; mt++) {
            a[mt][0] = fas(p0[rd[mt][0]] * p0[re[mt][0]]);
            a[mt][1] = fas(p0[rd[mt][1]] * p0[re[mt][1]]);
            a[mt][2] = fas(p1[rd[mt][0]] * p1[re[mt][0]]);
            a[mt][3] = fas(p1[rd[mt][1]] * p1[re[mt][1]]);
        }
        unsigned b[3][2];
        #pragma unroll
        for (int nt = 0; nt < 3; nt++) {
            int fc = cb + 8 * nt + g;
            b[nt][0] = sBu[(8 * ks + tg) * NW + fc];
            b[nt][1] = sBu[(8 * ks + tg + 4) * NW + fc];
        }
        #pragma unroll
        for (int mt = 0; mt < 2; mt++)
            #pragma unroll
            for (int nt = 0; nt < 3; nt++)
                mma8(c[mt][nt], a[mt][0], a[mt][1], a[mt][2], a[mt][3],
                     b[nt][0], b[nt][1]);
    }

    #pragma unroll
    for (int mt = 0; mt < 2; mt++)
        #pragma unroll
        for (int nt = 0; nt < 3; nt++) {
            int r0 = rb + 16 * mt + g, col = cb + 8 * nt + 2 * tg;
            *(float2*)&st[r0 * NW + col] =
                make_float2(c[mt][nt][0], c[mt][nt][1]);
            *(float2*)&st[(r0 + 8) * NW + col] =
                make_float2(c[mt][nt][2], c[mt][nt][3]);
        }
}

// ---------------------------------------------------------------------------
// Kernel 2: exclusive prefix scan over chunk axis. One element per thread.
// grid (BH, 45) x 256 threads = 11520 elements.
// ---------------------------------------------------------------------------
__global__ void k_scan() {
    const int head = blockIdx.x;
    float* base = g_state + (size_t)head * NC * ST_STRIDE +
                  blockIdx.y * blockDim.x + threadIdx.x;
    float run = 0.f;
    #pragma unroll
    for (int c = 0; c < NC; c++) {
        float t = base[(size_t)c * ST_STRIDE];
        base[(size_t)c * ST_STRIDE] = run;
        run += t;
    }
}

// ---------------------------------------------------------------------------
// Kernel 3: output. 512 threads, 2 CTAs/SM. Mirrored row tiles (34 steps per
// warp). Inter-z scalar, split across thread pairs.
// ---------------------------------------------------------------------------
__global__ __launch_bounds__(512, 2)
void k_main(const float* __restrict__ qin, const float* __restrict__ kin,
            const float* __restrict__ vin, float* __restrict__ out) {
    const int head = blockIdx.x, ch = blockIdx.y;
    extern __shared__ float sm[];
    float* sq  = sm;                    // [256][17], col16 = 1.0 pad
    float* sk  = sq + CS * 17;          // [256][17]
    float* sB  = sk + CS * 17;          // [256][72] V, later state[160][72]
    float* szs = sB + CS * NW;          // [256]
    int*   spd = (int*)(szs + 256);     // [160]
    int*   spe = spd + NP;
    float* sw  = (float*)(spe + NP);    // [160]
    float* swst = sw + NP;              // [160] w*state[:,64]
    unsigned* sBu = (unsigned*)sB;

    const float* qg = qin + ((size_t)head * LSEQ + (size_t)ch * CS) * DK;
    const float* kg = kin + ((size_t)head * LSEQ + (size_t)ch * CS) * DK;
    const float* vg = vin + ((size_t)head * LSEQ + (size_t)ch * CS) * DV;
    const float* st = g_state + (size_t)(head * NC + ch) * ST_STRIDE;

    const int tid = threadIdx.x, warp = tid >> 5, lane = tid & 31;
    const int wm = warp >> 1, wn = warp & 1, g = lane >> 2, tg = lane & 3;
    int rbase[2];
    rbase[0] = 16 * wm;
    rbase[1] = 240 - 16 * wm;

    for (int i = tid; i < CS * DK; i += 512) {
        int r = i >> 4, cc = i & 15;
        sq[r * 17 + cc] = f2tf(qg[i] * 0.25f);
        sk[r * 17 + cc] = f2tf(kg[i]);
    }
    if (tid < 256) { sq[tid * 17 + 16] = 1.0f; szs[tid] = 0.f; }
    for (int i = tid; i < CS * 16; i += 512) {
        int cc = i >> 4, f4 = (i & 15) * 4;
        *(uint4*)&sBu[cc * NW + f4] = *(const uint4*)&vg[cc * 64 + f4];
    }
    lut_build(spd, spe, sw, tid);
    __syncthreads();

    // Q fragments per mirrored tile (K=16 split as 2 x K=8)
    unsigned qf[2][2][4];
    #pragma unroll
    for (int mt = 0; mt < 2; mt++)
        #pragma unroll
        for (int ks = 0; ks < 2; ks++) {
            int r0 = rbase[mt] + g;
            qf[mt][ks][0] = fas(sq[r0 * 17 + 8 * ks + tg]);
            qf[mt][ks][1] = fas(sq[(r0 + 8) * 17 + 8 * ks + tg]);
            qf[mt][ks][2] = fas(sq[r0 * 17 + 8 * ks + tg + 4]);
            qf[mt][ks][3] = fas(sq[(r0 + 8) * 17 + 8 * ks + tg + 4]);
        }

    float c[2][4][4];
    #pragma unroll
    for (int mt = 0; mt < 2; mt++)
        #pragma unroll
        for (int nt = 0; nt < 4; nt++)
            #pragma unroll
            for (int u = 0; u < 4; u++) c[mt][nt][u] = 0.f;

    float zp[2][2];
    zp[0][0] = zp[0][1] = zp[1][0] = zp[1][1] = 0.f;
    const int srcA = (lane & ~3) + (tg >> 1), srcB = srcA + 2;
    const bool od = tg & 1;

    // ---- intra: barrier-free, per-tile column sweep ----
    #pragma unroll
    for (int mt = 0; mt < 2; mt++) {
        const int R = rbase[mt];
        const int nsteps = R / 8 + 2;       // cols [0, R+16)
        const int r0 = R + g;
        for (int js = 0; js < nsteps; js++) {
            int jc = 8 * js + g;
            unsigned b00 = fas(sk[jc * 17 + tg]);
            unsigned b01 = fas(sk[jc * 17 + tg + 4]);
            unsigned b10 = fas(sk[jc * 17 + 8 + tg]);
            unsigned b11 = fas(sk[jc * 17 + 8 + tg + 4]);
            // independent accumulators: the two K=8 mmas don't serialize
            float sfa[4] = {0.f, 0.f, 0.f, 0.f};
            float sfb[4] = {0.f, 0.f, 0.f, 0.f};
            mma8(sfa, qf[mt][0][0], qf[mt][0][1], qf[mt][0][2],
                 qf[mt][0][3], b00, b01);
            mma8(sfb, qf[mt][1][0], qf[mt][1][1], qf[mt][1][2],
                 qf[mt][1][3], b10, b11);
            int jg = 8 * js + 2 * tg;
            float s0 = sfa[0] + sfb[0], s1 = sfa[1] + sfb[1];
            float s2 = sfa[2] + sfb[2], s3 = sfa[3] + sfb[3];
            float v0 = (r0 >= jg)     ? fmaf(0.5f * s0, s0, s0 + 1.f) : 0.f;
            float v1 = (r0 >= jg + 1) ? fmaf(0.5f * s1, s1, s1 + 1.f) : 0.f;
            float v2 = (r0 + 8 >= jg)     ? fmaf(0.5f * s2, s2, s2 + 1.f) : 0.f;
            float v3 = (r0 + 8 >= jg + 1) ? fmaf(0.5f * s3, s3, s3 + 1.f) : 0.f;
            zp[mt][0] += v0 + v1;
            zp[mt][1] += v2 + v3;
            unsigned u0 = fas(v0), u1 = fas(v1);
            unsigned u2 = fas(v2), u3 = fas(v3);
            unsigned e0 = shflu(u0, srcA), o0 = shflu(u1, srcA);
            unsigned e1 = shflu(u2, srcA), o1 = shflu(u3, srcA);
            unsigned e2 = shflu(u0, srcB), o2 = shflu(u1, srcB);
            unsigned e3 = shflu(u2, srcB), o3 = shflu(u3, srcB);
            unsigned af0 = od ? o0 : e0;
            unsigned af1 = od ? o1 : e1;
            unsigned af2 = od ? o2 : e2;
            unsigned af3 = od ? o3 : e3;
            #pragma unroll
            for (int nt = 0; nt < 4; nt++) {
                int fc = 32 * wn + 8 * nt + g;
                unsigned bv0 = sBu[(8 * js + tg) * NW + fc];
                unsigned bv1 = sBu[(8 * js + tg + 4) * NW + fc];
                mma8(c[mt][nt], af0, af1, af2, af3, bv0, bv1);
            }
        }
    }

    // intra z merge: wn==0 warps own their rows exclusively
    if (wn == 0) {
        #pragma unroll
        for (int mt = 0; mt < 2; mt++)
            #pragma unroll
            for (int h = 0; h < 2; h++) {
                float v = zp[mt][h];
                v += __shfl_xor_sync(0xffffffffu, v, 1);
                v += __shfl_xor_sync(0xffffffffu, v, 2);
                if (tg == 0) szs[rbase[mt] + g + 8 * h] += v;
            }
    }
    __syncthreads();   // V reads + szs intra writes complete

    // restage sB <- w * scanned state [160][72]; swst <- w * state[:,64]
    for (int i = tid; i < NP * 16; i += 512) {
        int pp = i >> 4, f4 = (i & 15) * 4;
        float w = sw[pp];
        float4 vv = *(const float4*)&st[pp * NW + f4];
        *(uint4*)&sBu[pp * NW + f4] =
            make_uint4(fas(w * vv.x), fas(w * vv.y),
                       fas(w * vv.z), fas(w * vv.w));
    }
    if (tid < NP) swst[tid] = sw[tid] * st[tid * NW + 64];
    __syncthreads();

    // inter z (scalar, split across thread pairs):
    // z_inter[row] = sum_p q_d q_e * (w*state[p][64])
    {
        int row = tid >> 1, half = tid & 1;
        const float* qr = sq + row * 17;
        float zi = 0.f;
        int p0 = half ? 77 : 0, p1 = half ? 153 : 77;
        #pragma unroll 7
        for (int p = p0; p < p1; p++)
            zi = fmaf(qr[spd[p]] * qr[spe[p]], swst[p], zi);
        zi += __shfl_xor_sync(0xffffffffu, zi, 1);
        if (!half) szs[row] += zi;
    }

    // ---- inter: C[256x64] += A[256x160] @ Bstate[160x64], unrolled ----
    const int colb = 32 * wn;
    #pragma unroll 5
    for (int ks = 0; ks < 20; ks++) {
        int p0 = 8 * ks + tg, p1 = p0 + 4;
        int d0 = spd[p0], e0 = spe[p0];
        int d1 = spd[p1], e1 = spe[p1];
        unsigned a[2][4];
        #pragma unroll
        for (int mt = 0; mt < 2; mt++) {
            const float* qr0 = sq + (rbase[mt] + g) * 17;
            const float* qr1 = qr0 + 8 * 17;
            a[mt][0] = fas(qr0[d0] * qr0[e0]);
            a[mt][1] = fas(qr1[d0] * qr1[e0]);
            a[mt][2] = fas(qr0[d1] * qr0[e1]);
            a[mt][3] = fas(qr1[d1] * qr1[e1]);
        }
        unsigned b[4][2];
        #pragma unroll
        for (int nt = 0; nt < 4; nt++) {
            int fc = colb + 8 * nt + g;
            b[nt][0] = sBu[(8 * ks + tg) * NW + fc];
            b[nt][1] = sBu[(8 * ks + tg + 4) * NW + fc];
        }
        #pragma unroll
        for (int mt = 0; mt < 2; mt++)
            #pragma unroll
            for (int nt = 0; nt < 4; nt++)
                mma8(c[mt][nt], a[mt][0], a[mt][1], a[mt][2],
                     a[mt][3], b[nt][0], b[nt][1]);
    }
    __syncthreads();

    // ---- epilogue: divide by z, store ----
    float* og = out + ((size_t)head * LSEQ + (size_t)ch * CS) * DV;
    #pragma unroll
    for (int mt = 0; mt < 2; mt++) {
        int r0 = rbase[mt] + g;
        float z0 = 1.f / (szs[r0] + 1e-6f);
        float z1 = 1.f / (szs[r0 + 8] + 1e-6f);
        #pragma unroll
        for (int nt = 0; nt < 4; nt++) {
            int f = 32 * wn + 8 * nt + 2 * tg;
            *(float2*)&og[r0 * 64 + f] =
                make_float2(c[mt][nt][0] * z0, c[mt][nt][1] * z0);
            *(float2*)&og[(r0 + 8) * 64 + f] =
                make_float2(c[mt][nt][2] * z1, c[mt][nt][3] * z1);
        }
    }
}

// ---------------------------------------------------------------------------
extern "C" void kernel_launch(void* const* d_in, const int* in_sizes, int n_in,
                              void* d_out, int out_size) {
    const float* q = (const float*)d_in[0];
    const float* k = (const float*)d_in[1];
    const float* v = (const float*)d_in[2];
    float* out = (float*)d_out;

    const int smem1 = (CS * 17 + CS * NW + 3 * NP) * (int)sizeof(float);
    const int smem3 = (CS * 17 * 2 + CS * NW + 256 + 4 * NP) * (int)sizeof(float);

    cudaFuncSetAttribute(k_build, cudaFuncAttributeMaxDynamicSharedMemorySize, smem1);
    cudaFuncSetAttribute(k_main,  cudaFuncAttributeMaxDynamicSharedMemorySize, smem3);

    k_build<<<dim3(BH, NC), 480, smem1>>>(k, v);
    k_scan<<<dim3(BH, 45), 256>>>();
    k_main<<<dim3(BH, NC), 512, smem3>>>(q, k, v, out);
}

// round 11
// speedup vs baseline: 1.0623x; 1.0623x over previous
#include <cuda_runtime.h>
#include <cstdint>

#define BH   32
#define LSEQ 4096
#define DK   16
#define DV   64
#define CS   256
#define NC   16

// Symmetric-pair state: 136 pair rows (d<=e) + 16 linear rows + 1 ones row,
// padded to 160 rows x 72 cols (64 v-cols + 1 aux-sum col + 7 zero pads).
#define NP   160
#define NW   72
#define ST_STRIDE (NP * NW)   // 11520

__device__ float g_state[(size_t)BH * NC * ST_STRIDE];

__device__ __forceinline__ unsigned f2t(float x) {
    unsigned u;
    asm("cvt.rna.tf32.f32 %0, %1;" : "=r"(u) : "f"(x));
    return u;
}
__device__ __forceinline__ float f2tf(float x) { return __uint_as_float(f2t(x)); }
__device__ __forceinline__ unsigned fas(float x) { return __float_as_uint(x); }
__device__ __forceinline__ unsigned shflu(unsigned v, int src) {
    return __shfl_sync(0xffffffffu, v, src);
}

__device__ __forceinline__ void mma8(float* c, unsigned a0, unsigned a1,
                                     unsigned a2, unsigned a3,
                                     unsigned b0, unsigned b1) {
    asm volatile(
        "mma.sync.aligned.m16n8k8.row.col.f32.tf32.tf32.f32 "
        "{%0,%1,%2,%3},{%4,%5,%6,%7},{%8,%9},{%0,%1,%2,%3};"
        : "+f"(c[0]), "+f"(c[1]), "+f"(c[2]), "+f"(c[3])
        : "r"(a0), "r"(a1), "r"(a2), "r"(a3), "r"(b0), "r"(b1));
}

// p -> (d, e, w).  d,e in [0,16]; index 16 hits the pad column (=1.0f).
__device__ __forceinline__ void lut_build(int* spd, int* spe, float* sw, int tid) {
    if (tid < NP) {
        int p = tid, d = 0, e;
        float w;
        if (p < 136) {
            int base = 0;
            while (base + (16 - d) <= p) { base += 16 - d; d++; }
            e = d + (p - base);
            w = (d == e) ? 0.5f : 1.0f;
        } else if (p < 152) { d = p - 136; e = 16; w = 1.f; }
        else if (p == 152) { d = 16; e = 16; w = 1.f; }
        else               { d = 16; e = 16; w = 0.f; }
        spd[p] = d; spe[p] = e; sw[p] = w;
    }
}

// ---------------------------------------------------------------------------
// Kernel 1: state build = single GEMM  st[160x72] = A[160x256] @ B[256x72]
// Full B staged once; ONE barrier; unrolled 32-step mma stream.
// 480 threads = 15 warps, 2 CTAs/SM (regs capped).
// ---------------------------------------------------------------------------
__global__ __launch_bounds__(480, 2)
void k_build(const float* __restrict__ kin, const float* __restrict__ vin) {
    const int head = blockIdx.x, ch = blockIdx.y;
    extern __shared__ float sm[];
    float* sk = sm;                     // [256][17], col 16 = 1.0 pad
    float* sB = sk + CS * 17;           // [256][72] full V + aux
    int*   spd = (int*)(sB + CS * NW);  // [160]
    int*   spe = spd + NP;              // [160]
    float* sw  = (float*)(spe + NP);    // [160]
    unsigned* sBu = (unsigned*)sB;

    const float* kg = kin + ((size_t)head * LSEQ + (size_t)ch * CS) * DK;
    const float* vg = vin + ((size_t)head * LSEQ + (size_t)ch * CS) * DV;
    float* st = g_state + (size_t)(head * NC + ch) * ST_STRIDE;

    const int tid = threadIdx.x, warp = tid >> 5, lane = tid & 31;
    const int wm = warp / 3, wn = warp % 3, g = lane >> 2, tg = lane & 3;
    const int rb = 32 * wm, cb = 24 * wn;

    for (int i = tid; i < CS * DK; i += 480)
        sk[(i >> 4) * 17 + (i & 15)] = f2tf(kg[i]);
    for (int i = tid; i < CS; i += 480) sk[i * 17 + 16] = 1.0f;
    for (int i = tid; i < CS * 18; i += 480) {
        int cc = i / 18, f4 = (i - cc * 18) * 4;
        uint4 w;
        if (f4 < 64) {
            float4 vv = *(const float4*)&vg[cc * 64 + f4];
            w = make_uint4(f2t(vv.x), f2t(vv.y), f2t(vv.z), f2t(vv.w));
        } else {
            w = make_uint4(f4 == 64 ? 0x3f800000u : 0u, 0u, 0u, 0u);
        }
        *(uint4*)&sBu[cc * NW + f4] = w;
    }
    lut_build(spd, spe, sw, tid);
    __syncthreads();

    int rd[2][2], re[2][2];
    #pragma unroll
    for (int mt = 0; mt < 2; mt++) {
        int r0 = rb + 16 * mt + g;
        rd[mt][0] = spd[r0];     re[mt][0] = spe[r0];
        rd[mt][1] = spd[r0 + 8]; re[mt][1] = spe[r0 + 8];
    }

    float c[2][3][4];
    #pragma unroll
    for (int mt = 0; mt < 2; mt++)
        #pragma unroll
        for (int nt = 0; nt < 3; nt++)
            #pragma unroll
            for (int u = 0; u < 4; u++) c[mt][nt][u] = 0.f;

    #pragma unroll 4
    for (int ks = 0; ks < 32; ks++) {
        const float* p0 = sk + (8 * ks + tg) * 17;
        const float* p1 = p0 + 4 * 17;
        unsigned a[2][4];
        #pragma unroll
        for (int mt = 0; mt < 2; mt++) {
            a[mt][0] = fas(p0[rd[mt][0]] * p0[re[mt][0]]);
            a[mt][1] = fas(p0[rd[mt][1]] * p0[re[mt][1]]);
            a[mt][2] = fas(p1[rd[mt][0]] * p1[re[mt][0]]);
            a[mt][3] = fas(p1[rd[mt][1]] * p1[re[mt][1]]);
        }
        unsigned b[3][2];
        #pragma unroll
        for (int nt = 0; nt < 3; nt++) {
            int fc = cb + 8 * nt + g;
            b[nt][0] = sBu[(8 * ks + tg) * NW + fc];
            b[nt][1] = sBu[(8 * ks + tg + 4) * NW + fc];
        }
        #pragma unroll
        for (int mt = 0; mt < 2; mt++)
            #pragma unroll
            for (int nt = 0; nt < 3; nt++)
                mma8(c[mt][nt], a[mt][0], a[mt][1], a[mt][2], a[mt][3],
                     b[nt][0], b[nt][1]);
    }

    #pragma unroll
    for (int mt = 0; mt < 2; mt++)
        #pragma unroll
        for (int nt = 0; nt < 3; nt++) {
            int r0 = rb + 16 * mt + g, col = cb + 8 * nt + 2 * tg;
            *(float2*)&st[r0 * NW + col] =
                make_float2(c[mt][nt][0], c[mt][nt][1]);
            *(float2*)&st[(r0 + 8) * NW + col] =
                make_float2(c[mt][nt][2], c[mt][nt][3]);
        }
}

// ---------------------------------------------------------------------------
// Kernel 2: exclusive prefix scan over chunk axis. One element per thread;
// all 16 loads issued up front (MLP=16), prefix in registers, store back.
// grid (BH, 45) x 256 threads = 11520 elements.
// ---------------------------------------------------------------------------
__global__ void k_scan() {
    float* base = g_state + (size_t)blockIdx.x * NC * ST_STRIDE +
                  blockIdx.y * blockDim.x + threadIdx.x;
    float v[NC];
    #pragma unroll
    for (int c = 0; c < NC; c++) v[c] = base[(size_t)c * ST_STRIDE];
    float run = 0.f;
    #pragma unroll
    for (int c = 0; c < NC; c++) {
        float t = v[c];
        v[c] = run;
        run += t;
    }
    #pragma unroll
    for (int c = 0; c < NC; c++) base[(size_t)c * ST_STRIDE] = v[c];
}

// ---------------------------------------------------------------------------
// Kernel 3: output. 512 threads, 2 CTAs/SM. Mirrored row tiles (34 steps per
// warp). Inter-z computed scalar (no 5th accumulator tile, no divergence).
// ---------------------------------------------------------------------------
__global__ __launch_bounds__(512, 2)
void k_main(const float* __restrict__ qin, const float* __restrict__ kin,
            const float* __restrict__ vin, float* __restrict__ out) {
    const int head = blockIdx.x, ch = blockIdx.y;
    extern __shared__ float sm[];
    float* sq  = sm;                    // [256][17], col16 = 1.0 pad
    float* sk  = sq + CS * 17;          // [256][17]
    float* sB  = sk + CS * 17;          // [256][72] V, later state[160][72]
    float* szs = sB + CS * NW;          // [256]
    int*   spd = (int*)(szs + 256);     // [160]
    int*   spe = spd + NP;
    float* sw  = (float*)(spe + NP);    // [160]
    float* swst = sw + NP;              // [160] w*state[:,64]
    unsigned* sBu = (unsigned*)sB;

    const float* qg = qin + ((size_t)head * LSEQ + (size_t)ch * CS) * DK;
    const float* kg = kin + ((size_t)head * LSEQ + (size_t)ch * CS) * DK;
    const float* vg = vin + ((size_t)head * LSEQ + (size_t)ch * CS) * DV;
    const float* st = g_state + (size_t)(head * NC + ch) * ST_STRIDE;

    const int tid = threadIdx.x, warp = tid >> 5, lane = tid & 31;
    const int wm = warp >> 1, wn = warp & 1, g = lane >> 2, tg = lane & 3;
    int rbase[2];
    rbase[0] = 16 * wm;
    rbase[1] = 240 - 16 * wm;

    for (int i = tid; i < CS * DK; i += 512) {
        int r = i >> 4, cc = i & 15;
        sq[r * 17 + cc] = f2tf(qg[i] * 0.25f);
        sk[r * 17 + cc] = f2tf(kg[i]);
    }
    if (tid < 256) { sq[tid * 17 + 16] = 1.0f; szs[tid] = 0.f; }
    for (int i = tid; i < CS * 16; i += 512) {
        int cc = i >> 4, f4 = (i & 15) * 4;
        float4 v = *(const float4*)&vg[cc * 64 + f4];
        *(uint4*)&sBu[cc * NW + f4] =
            make_uint4(f2t(v.x), f2t(v.y), f2t(v.z), f2t(v.w));
    }
    lut_build(spd, spe, sw, tid);
    __syncthreads();

    // Q fragments per mirrored tile (K=16 split as 2 x K=8)
    unsigned qf[2][2][4];
    #pragma unroll
    for (int mt = 0; mt < 2; mt++)
        #pragma unroll
        for (int ks = 0; ks < 2; ks++) {
            int r0 = rbase[mt] + g;
            qf[mt][ks][0] = fas(sq[r0 * 17 + 8 * ks + tg]);
            qf[mt][ks][1] = fas(sq[(r0 + 8) * 17 + 8 * ks + tg]);
            qf[mt][ks][2] = fas(sq[r0 * 17 + 8 * ks + tg + 4]);
            qf[mt][ks][3] = fas(sq[(r0 + 8) * 17 + 8 * ks + tg + 4]);
        }

    float c[2][4][4];
    #pragma unroll
    for (int mt = 0; mt < 2; mt++)
        #pragma unroll
        for (int nt = 0; nt < 4; nt++)
            #pragma unroll
            for (int u = 0; u < 4; u++) c[mt][nt][u] = 0.f;

    float zp[2][2];
    zp[0][0] = zp[0][1] = zp[1][0] = zp[1][1] = 0.f;
    const int srcA = (lane & ~3) + (tg >> 1), srcB = srcA + 2;
    const bool od = tg & 1;

    // ---- intra: barrier-free, per-tile column sweep ----
    #pragma unroll
    for (int mt = 0; mt < 2; mt++) {
        const int R = rbase[mt];
        const int nsteps = R / 8 + 2;       // cols [0, R+16)
        const int r0 = R + g;
        for (int js = 0; js < nsteps; js++) {
            int jc = 8 * js + g;
            unsigned b00 = fas(sk[jc * 17 + tg]);
            unsigned b01 = fas(sk[jc * 17 + tg + 4]);
            unsigned b10 = fas(sk[jc * 17 + 8 + tg]);
            unsigned b11 = fas(sk[jc * 17 + 8 + tg + 4]);
            float sf[4] = {0.f, 0.f, 0.f, 0.f};
            mma8(sf, qf[mt][0][0], qf[mt][0][1], qf[mt][0][2],
                 qf[mt][0][3], b00, b01);
            mma8(sf, qf[mt][1][0], qf[mt][1][1], qf[mt][1][2],
                 qf[mt][1][3], b10, b11);
            int jg = 8 * js + 2 * tg;
            float s0 = sf[0], s1 = sf[1], s2 = sf[2], s3 = sf[3];
            float v0 = (r0 >= jg)     ? fmaf(0.5f * s0, s0, s0 + 1.f) : 0.f;
            float v1 = (r0 >= jg + 1) ? fmaf(0.5f * s1, s1, s1 + 1.f) : 0.f;
            float v2 = (r0 + 8 >= jg)     ? fmaf(0.5f * s2, s2, s2 + 1.f) : 0.f;
            float v3 = (r0 + 8 >= jg + 1) ? fmaf(0.5f * s3, s3, s3 + 1.f) : 0.f;
            zp[mt][0] += v0 + v1;
            zp[mt][1] += v2 + v3;
            unsigned u0 = f2t(v0), u1 = f2t(v1);
            unsigned u2 = f2t(v2), u3 = f2t(v3);
            unsigned e0 = shflu(u0, srcA), o0 = shflu(u1, srcA);
            unsigned e1 = shflu(u2, srcA), o1 = shflu(u3, srcA);
            unsigned e2 = shflu(u0, srcB), o2 = shflu(u1, srcB);
            unsigned e3 = shflu(u2, srcB), o3 = shflu(u3, srcB);
            unsigned af0 = od ? o0 : e0;
            unsigned af1 = od ? o1 : e1;
            unsigned af2 = od ? o2 : e2;
            unsigned af3 = od ? o3 : e3;
            #pragma unroll
            for (int nt = 0; nt < 4; nt++) {
                int fc = 32 * wn + 8 * nt + g;
                unsigned bv0 = sBu[(8 * js + tg) * NW + fc];
                unsigned bv1 = sBu[(8 * js + tg + 4) * NW + fc];
                mma8(c[mt][nt], af0, af1, af2, af3, bv0, bv1);
            }
        }
    }

    // intra z merge: wn==0 warps own their rows exclusively
    if (wn == 0) {
        #pragma unroll
        for (int mt = 0; mt < 2; mt++)
            #pragma unroll
            for (int h = 0; h < 2; h++) {
                float v = zp[mt][h];
                v += __shfl_xor_sync(0xffffffffu, v, 1);
                v += __shfl_xor_sync(0xffffffffu, v, 2);
                if (tg == 0) szs[rbase[mt] + g + 8 * h] += v;
            }
    }
    __syncthreads();   // V reads + szs intra writes complete

    // restage sB <- w * scanned state [160][72]; swst <- w * state[:,64]
    for (int i = tid; i < NP * 16; i += 512) {
        int pp = i >> 4, f4 = (i & 15) * 4;
        float w = sw[pp];
        float4 vv = *(const float4*)&st[pp * NW + f4];
        *(uint4*)&sBu[pp * NW + f4] =
            make_uint4(f2t(w * vv.x), f2t(w * vv.y),
                       f2t(w * vv.z), f2t(w * vv.w));
    }
    if (tid < NP) swst[tid] = sw[tid] * st[tid * NW + 64];
    __syncthreads();

    // inter z (scalar): z_inter[row] = sum_p q_d q_e * (w*state[p][64])
    if (tid < 256) {
        const float* qr = sq + tid * 17;
        float zi = 0.f;
        #pragma unroll 8
        for (int p = 0; p < 153; p++)
            zi = fmaf(qr[spd[p]] * qr[spe[p]], swst[p], zi);
        szs[tid] += zi;
    }

    // ---- inter: C[256x64] += A[256x160] @ Bstate[160x64], unrolled ----
    const int colb = 32 * wn;
    #pragma unroll 5
    for (int ks = 0; ks < 20; ks++) {
        int p0 = 8 * ks + tg, p1 = p0 + 4;
        int d0 = spd[p0], e0 = spe[p0];
        int d1 = spd[p1], e1 = spe[p1];
        unsigned a[2][4];
        #pragma unroll
        for (int mt = 0; mt < 2; mt++) {
            const float* qr0 = sq + (rbase[mt] + g) * 17;
            const float* qr1 = qr0 + 8 * 17;
            a[mt][0] = fas(qr0[d0] * qr0[e0]);
            a[mt][1] = fas(qr1[d0] * qr1[e0]);
            a[mt][2] = fas(qr0[d1] * qr0[e1]);
            a[mt][3] = fas(qr1[d1] * qr1[e1]);
        }
        unsigned b[4][2];
        #pragma unroll
        for (int nt = 0; nt < 4; nt++) {
            int fc = colb + 8 * nt + g;
            b[nt][0] = sBu[(8 * ks + tg) * NW + fc];
            b[nt][1] = sBu[(8 * ks + tg + 4) * NW + fc];
        }
        #pragma unroll
        for (int mt = 0; mt < 2; mt++)
            #pragma unroll
            for (int nt = 0; nt < 4; nt++)
                mma8(c[mt][nt], a[mt][0], a[mt][1], a[mt][2],
                     a[mt][3], b[nt][0], b[nt][1]);
    }
    __syncthreads();

    // ---- epilogue: divide by z, store ----
    float* og = out + ((size_t)head * LSEQ + (size_t)ch * CS) * DV;
    #pragma unroll
    for (int mt = 0; mt < 2; mt++) {
        int r0 = rbase[mt] + g;
        float z0 = 1.f / (szs[r0] + 1e-6f);
        float z1 = 1.f / (szs[r0 + 8] + 1e-6f);
        #pragma unroll
        for (int nt = 0; nt < 4; nt++) {
            int f = 32 * wn + 8 * nt + 2 * tg;
            *(float2*)&og[r0 * 64 + f] =
                make_float2(c[mt][nt][0] * z0, c[mt][nt][1] * z0);
            *(float2*)&og[(r0 + 8) * 64 + f] =
                make_float2(c[mt][nt][2] * z1, c[mt][nt][3] * z1);
        }
    }
}

// ---------------------------------------------------------------------------
extern "C" void kernel_launch(void* const* d_in, const int* in_sizes, int n_in,
                              void* d_out, int out_size) {
    const float* q = (const float*)d_in[0];
    const float* k = (const float*)d_in[1];
    const float* v = (const float*)d_in[2];
    float* out = (float*)d_out;

    const int smem1 = (CS * 17 + CS * NW + 3 * NP) * (int)sizeof(float);
    const int smem3 = (CS * 17 * 2 + CS * NW + 256 + 4 * NP) * (int)sizeof(float);

    cudaFuncSetAttribute(k_build, cudaFuncAttributeMaxDynamicSharedMemorySize, smem1);
    cudaFuncSetAttribute(k_main,  cudaFuncAttributeMaxDynamicSharedMemorySize, smem3);

    k_build<<<dim3(BH, NC), 480, smem1>>>(k, v);
    k_scan<<<dim3(BH, 45), 256>>>();
    k_main<<<dim3(BH, NC), 512, smem3>>>(q, k, v, out);
}